// round 17
// baseline (speedup 1.0000x reference)
#include <cuda_runtime.h>
#include <cuda_fp16.h>
#include <math.h>

#define HIDDEN 64
#define MBATCH 32
#define ATOM   64
#define NUM_RBF 300

#define S_INT   512
#define TAB_ROWS 513                    // row s = h(s*H_STEP), s in [0,512]
#define H_STEP  (10.0f / 512.0f)
#define INV_H   51.2f

typedef unsigned long long u64;

// device scratch (no allocations allowed)
__device__ __align__(16) unsigned g_table_h[515 * 32];   // fp16x2 table, row=128B
__device__ unsigned g_bar;                               // monotonic grid barrier

__device__ __forceinline__ float softplus_f(float v) {
    return fmaxf(v, 0.0f) + log1pf(expf(-fabsf(v)));
}

// packed f32x2 helpers (Blackwell FFMA2 / FADD2)
__device__ __forceinline__ u64 fma2(u64 a, u64 b, u64 c) {
    u64 d; asm("fma.rn.f32x2 %0, %1, %2, %3;" : "=l"(d) : "l"(a), "l"(b), "l"(c)); return d;
}
__device__ __forceinline__ u64 add2(u64 a, u64 b) {
    u64 d; asm("add.rn.f32x2 %0, %1, %2;" : "=l"(d) : "l"(a), "l"(b)); return d;
}
__device__ __forceinline__ u64 pack2(float a, float b) {
    u64 d; asm("mov.b64 %0, {%1, %2};" : "=l"(d) : "f"(a), "f"(b)); return d;
}
__device__ __forceinline__ float2 unpk2(u64 v) {
    float2 f; asm("mov.b64 {%0, %1}, %2;" : "=f"(f.x), "=f"(f.y) : "l"(v)); return f;
}
__device__ __forceinline__ u64 dup2(float v) {
    u64 d; asm("mov.b64 %0, {%1, %1};" : "=l"(d) : "f"(v)); return d;
}
__device__ __forceinline__ unsigned h2bits(float w) {
    __half2 h = __float2half2_rn(w);
    return *reinterpret_cast<unsigned*>(&h);
}
__device__ __forceinline__ __half2 bits2h(unsigned u) {
    return *reinterpret_cast<__half2*>(&u);
}

// ---------------------------------------------------------------------------
// FUSED kernel: 128 blocks = (m, j-group of 16), 1024 threads.
//   Phase A (full-occupancy rebuild): register prefetch of x/W1/Wd2/dist;
//     A1: 4 (CTA127: 5) table samples, thread=(q,c,quarter)+shfl reduce,
//         Wd1 read direct from global;
//     A2: v1 GEMM into smem; A3: W4 + biases + tiled transposes.
//   Grid barrier; Phase B: depth-2 pipelined main loop + fused epilogue.
// ---------------------------------------------------------------------------
// smem floats: V1s 4096 | W2Ts 4096 | W3Ts 4096 | B2s 64 | B3s 64 |
//              W4s 4096 | PARTs 4096 | PAIRs 1024 | V2s 1024 = 22656 = 90624 B
#define MAIN_SMEM (22656 * 4)
#define RBPAD 37

__global__ void __launch_bounds__(1024) fused_kernel(
    const float* __restrict__ x, const float* __restrict__ dist,
    const float* __restrict__ W1, const float* __restrict__ b1,
    const float* __restrict__ W2, const float* __restrict__ b2,
    const float* __restrict__ W3, const float* __restrict__ b3,
    const float* __restrict__ Wd1, const float* __restrict__ bd1,
    const float* __restrict__ Wd2, const float* __restrict__ bd2,
    float* __restrict__ out)
{
    extern __shared__ float sh[];
    float* V1s  = sh;                     // 4096
    float* W2Ts = V1s + 4096;             // 4096
    float* W3Ts = W2Ts + 4096;            // 4096
    float* B2s  = W3Ts + 4096;            // 64
    float* B3s  = B2s + 64;               // 64
    float* W4s  = B3s + 64;               // 4096
    float* PARTs= W4s + 4096;             // 4096
    float* PAIRs= PARTs + 4096;           // 1024
    float* V2s  = PAIRs + 1024;           // 1024

    const int tid = threadIdx.x;
    const int bid = blockIdx.x;
    const int m  = bid >> 2;
    const int j0 = (bid & 3) << 4;

    // -------- register prefetch: all cold per-CTA loads in flight NOW --------
    const float4 x_reg  = ((const float4*)(x + m * 4096))[tid];
    const float4 w1_reg = ((const float4*)W1)[tid];
    const float4 wd2_reg= ((const float4*)Wd2)[tid];
    const float  dval   = dist[(m * 64 + (tid >> 4)) * 64 + j0 + (tid & 15)];

    // ------------------- Phase A1: table samples (all threads) -------------------
    {
        float* Wd2_s = PARTs;             // 64 x 65 = 4160
        float* rbf_s = PARTs + 4160;      // 5 x 37 = 185
        float* g_s   = PARTs + 4352;      // 5 x 64 = 320

        const int s0 = bid << 2;
        const int NS = (bid == 127) ? 5 : 4;
        const float dlo = (float)s0 * H_STEP;
        const float dhi = (float)(s0 + NS - 1) * H_STEP;
        int R0 = (int)ceilf((dlo - 1.5f) * 10.0f); if (R0 < 0) R0 = 0;
        int R1 = (int)floorf((dhi + 1.5f) * 10.0f); if (R1 > NUM_RBF - 1) R1 = NUM_RBF - 1;
        const int RW = R1 - R0 + 1;       // <= 34

        // stage Wd2 (from prefetched register)
        {
            int e = tid << 2;
            float* dstp = Wd2_s + (e >> 6) * 65 + (e & 63);
            dstp[0] = wd2_reg.x; dstp[1] = wd2_reg.y;
            dstp[2] = wd2_reg.z; dstp[3] = wd2_reg.w;
        }
        // windowed RBF values
        if (tid < 5 * RBPAD) {
            int q = tid / RBPAD, rr = tid - q * RBPAD;
            float val = 0.0f;
            if (rr < RW && q < NS) {
                float dd = (float)(s0 + q) * H_STEP;
                float u = dd - 0.1f * (float)(R0 + rr);
                val = __expf(-10.0f * u * u);
            }
            rbf_s[tid] = val;
        }
        __syncthreads();

        const int part = tid & 3;
        const int c = (tid >> 2) & 63;
        // window sum: 4-way split + shfl reduce; Wd1 direct from global
        for (int q = tid >> 8; q < NS; q += 4) {
            const float* wrow = Wd1 + c * NUM_RBF + R0;
            const float* rrow = rbf_s + q * RBPAD;
            float p = 0.0f;
            #pragma unroll 3
            for (int j = part; j < RW; j += 4)
                p = fmaf(__ldg(wrow + j), rrow[j], p);
            p += __shfl_xor_sync(0xFFFFFFFFu, p, 1);
            p += __shfl_xor_sync(0xFFFFFFFFu, p, 2);
            if (part == 0) g_s[q * 64 + c] = softplus_f(p + bd1[c]);
        }
        __syncthreads();
        // layer 2: 4-way split over k
        for (int q = tid >> 8; q < NS; q += 4) {
            const float* w2row = Wd2_s + c * 65 + part * 16;
            const float* gg = g_s + q * 64 + part * 16;
            float qv = 0.0f;
            #pragma unroll
            for (int k = 0; k < 16; k++) qv = fmaf(w2row[k], gg[k], qv);
            qv += __shfl_xor_sync(0xFFFFFFFFu, qv, 1);
            qv += __shfl_xor_sync(0xFFFFFFFFu, qv, 2);
            if (part == 0)
                ((__half*)g_table_h)[(s0 + q) * 64 + c] =
                    __float2half_rn(softplus_f(qv + bd2[c]));
        }
        __syncthreads();
    }

    // ------------------- Phase A2: v1 = x[m] @ W1^T + b1 -> V1s -------------------
    {
        float* W1p = W4s;                // 64 x 68 = 4352 (spans into PARTs)
        float* xp  = W4s + 4352;         // 64 x 68
        {
            int e = tid << 2;
            *(float4*)(W1p + (e >> 6) * 68 + (e & 63)) = w1_reg;
            *(float4*)(xp  + (e >> 6) * 68 + (e & 63)) = x_reg;
        }
        __syncthreads();

        const int ii = tid & 63;         // source atom row
        const int oh = tid >> 6;         // output quad 0..15
        float4 acc = make_float4(0.f, 0.f, 0.f, 0.f);
        const float* xr = xp + ii * 68;
        const float* wr = W1p + oh * 4 * 68;
        #pragma unroll
        for (int c4 = 0; c4 < 16; c4++) {
            float4 xv = *(const float4*)(xr + c4 * 4);
            float4 w0 = *(const float4*)(wr + 0 * 68 + c4 * 4);
            float4 w1 = *(const float4*)(wr + 1 * 68 + c4 * 4);
            float4 w2 = *(const float4*)(wr + 2 * 68 + c4 * 4);
            float4 w3 = *(const float4*)(wr + 3 * 68 + c4 * 4);
            acc.x = fmaf(xv.x, w0.x, fmaf(xv.y, w0.y, fmaf(xv.z, w0.z, fmaf(xv.w, w0.w, acc.x))));
            acc.y = fmaf(xv.x, w1.x, fmaf(xv.y, w1.y, fmaf(xv.z, w1.z, fmaf(xv.w, w1.w, acc.y))));
            acc.z = fmaf(xv.x, w2.x, fmaf(xv.y, w2.y, fmaf(xv.z, w2.z, fmaf(xv.w, w2.w, acc.z))));
            acc.w = fmaf(xv.x, w3.x, fmaf(xv.y, w3.y, fmaf(xv.z, w3.z, fmaf(xv.w, w3.w, acc.w))));
        }
        float4 bv = *(const float4*)(b1 + oh * 4);
        acc.x += bv.x; acc.y += bv.y; acc.z += bv.z; acc.w += bv.w;
        *(float4*)(V1s + ii * 64 + oh * 4) = acc;
        __syncthreads();
    }

    // ------------------- Phase A3: W4 (from prefetched dval), biases, transposes ---
    {
        float t = dval * INV_H;
        int k = __float2int_rn(t);
        k = min(max(k, 1), S_INT - 1);
        float u = t - (float)k;
        float wm = 0.5f * u * (u - 1.0f);
        float w0 = 1.0f - u * u;
        float wp = 0.5f * u * (u + 1.0f);
        float4 wk;
        wk.x = __uint_as_float(h2bits(wm));
        wk.y = __uint_as_float(h2bits(w0));
        wk.z = __uint_as_float(h2bits(wp));
        wk.w = __int_as_float((k - 1) << 7);   // byte offset of first tap row
        ((float4*)W4s)[tid] = wk;

        if (tid < 64) B2s[tid] = b2[tid];
        else if (tid < 128) B3s[tid - 64] = b3[tid - 64];
    }
    // W2^T / W3^T via padded tile: coalesced LDG, conflict-free STS/LDS
    {
        float* Ttile = PARTs;            // 64 x 65
        #pragma unroll 4
        for (int k = 0; k < 4; k++) {
            int idx = tid + (k << 10);
            Ttile[(idx >> 6) * 65 + (idx & 63)] = __ldg(&W2[idx]);
        }
        __syncthreads();
        #pragma unroll 4
        for (int k = 0; k < 4; k++) {
            int idx = tid + (k << 10);
            W2Ts[idx] = Ttile[(idx & 63) * 65 + (idx >> 6)];
        }
        __syncthreads();
        #pragma unroll 4
        for (int k = 0; k < 4; k++) {
            int idx = tid + (k << 10);
            Ttile[(idx >> 6) * 65 + (idx & 63)] = __ldg(&W3[idx]);
        }
        __syncthreads();
        #pragma unroll 4
        for (int k = 0; k < 4; k++) {
            int idx = tid + (k << 10);
            W3Ts[idx] = Ttile[(idx & 63) * 65 + (idx >> 6)];
        }
    }

    // ------------------- Grid barrier (table visibility) -------------------
    __threadfence();
    __syncthreads();
    if (tid == 0) {
        unsigned old = atomicAdd(&g_bar, 1u);
        unsigned target = (old & ~127u) + 128u;
        while (*((volatile unsigned*)&g_bar) < target) { __nanosleep(64); }
        __threadfence();
    }
    __syncthreads();

    // ------------------- Phase B: depth-2 pipelined main loop -------------------
    const int warp  = tid >> 5;
    const int jj    = warp & 15;     // destination atom
    const int ihalf = warp >> 4;     // 0..1 : i-range half
    const int t     = tid & 31;
    const int half  = t >> 4;        // even/odd i within the half-warp
    const int q     = t & 15;        // channel quad: channels 4q..4q+3

    u64 acc0 = 0ull, acc1 = 0ull;
    const char* tbg = (const char*)g_table_h + (q << 3);    // GLOBAL, L1-cached
    const char* v1b = (const char*)V1s + (q << 4);
    const float4* W4v = ((const float4*)W4s) + jj;
    const int i0 = (ihalf << 5) + half;                     // start i, step 2

    float4 wk = W4v[i0 << 4];
    int koff = __float_as_int(wk.w);
    uint2 r0 = __ldg((const uint2*)(tbg + koff));
    uint2 r1 = __ldg((const uint2*)(tbg + koff + 128));
    uint2 r2 = __ldg((const uint2*)(tbg + koff + 256));
    ulonglong2 vv = *(const ulonglong2*)(v1b + (i0 << 8));

    #pragma unroll 4
    for (int ii = 0; ii < 16; ii++) {
        float4 wk_n = wk; uint2 s0 = r0, s1 = r1, s2 = r2; ulonglong2 vv_n = vv;
        if (ii < 15) {
            const int inext = i0 + ((ii + 1) << 1);
            wk_n = W4v[inext << 4];
            int koff_n = __float_as_int(wk_n.w);
            s0 = __ldg((const uint2*)(tbg + koff_n));
            s1 = __ldg((const uint2*)(tbg + koff_n + 128));
            s2 = __ldg((const uint2*)(tbg + koff_n + 256));
            vv_n = *(const ulonglong2*)(v1b + (inext << 8));
        }
        __half2 wm2 = bits2h(__float_as_uint(wk.x));
        __half2 w02 = bits2h(__float_as_uint(wk.y));
        __half2 wp2 = bits2h(__float_as_uint(wk.z));
        __half2 hA = __hfma2(wm2, bits2h(r0.x),
                     __hfma2(w02, bits2h(r1.x), __hmul2(wp2, bits2h(r2.x))));
        __half2 hB = __hfma2(wm2, bits2h(r0.y),
                     __hfma2(w02, bits2h(r1.y), __hmul2(wp2, bits2h(r2.y))));
        float2 fA = __half22float2(hA);
        float2 fB = __half22float2(hB);
        acc0 = fma2(vv.x, pack2(fA.x, fA.y), acc0);
        acc1 = fma2(vv.y, pack2(fB.x, fB.y), acc1);
        wk = wk_n; r0 = s0; r1 = s1; r2 = s2; vv = vv_n;
    }
    {
        const int slice = (ihalf << 1) | half;              // 0..3
        ulonglong2 r; r.x = acc0; r.y = acc1;
        ((ulonglong2*)PARTs)[slice * 256 + (jj << 4) + q] = r;
    }
    __syncthreads();

    // reduce 4 slices
    if (tid < 256) {
        const ulonglong2* pp = (const ulonglong2*)PARTs;
        ulonglong2 a0 = pp[tid];
        ulonglong2 a1 = pp[256 + tid];
        ulonglong2 a2 = pp[512 + tid];
        ulonglong2 a3 = pp[768 + tid];
        ulonglong2 r;
        r.x = add2(add2(a0.x, a1.x), add2(a2.x, a3.x));
        r.y = add2(add2(a0.y, a1.y), add2(a2.y, a3.y));
        ((ulonglong2*)PAIRs)[tid] = r;
    }
    __syncthreads();

    // epilogue: 8 warps, each handles 2 j-rows; lane = output pair (2t,2t+1)
    if (tid < 256) {
        const int g  = tid >> 5;      // 0..7
        const int tt = tid & 31;
        const int jj0 = g, jj1 = g + 8;

        u64 a0, a1;
        {
            u64 bp = ((const u64*)B2s)[tt];
            a0 = bp; a1 = bp;
            const float4* pr0 = (const float4*)(PAIRs + jj0 * 64);
            const float4* pr1 = (const float4*)(PAIRs + jj1 * 64);
            const u64* wv = (const u64*)W2Ts;
            #pragma unroll 4
            for (int c4 = 0; c4 < 16; c4++) {
                float4 p0 = pr0[c4];
                float4 p1 = pr1[c4];
                u64 w0 = wv[(c4 * 4 + 0) * 32 + tt];
                u64 w1 = wv[(c4 * 4 + 1) * 32 + tt];
                u64 w2 = wv[(c4 * 4 + 2) * 32 + tt];
                u64 w3 = wv[(c4 * 4 + 3) * 32 + tt];
                a0 = fma2(dup2(p0.x), w0, a0); a1 = fma2(dup2(p1.x), w0, a1);
                a0 = fma2(dup2(p0.y), w1, a0); a1 = fma2(dup2(p1.y), w1, a1);
                a0 = fma2(dup2(p0.z), w2, a0); a1 = fma2(dup2(p1.z), w2, a1);
                a0 = fma2(dup2(p0.w), w3, a0); a1 = fma2(dup2(p1.w), w3, a1);
            }
            float2 f0 = unpk2(a0), f1 = unpk2(a1);
            ((u64*)V2s)[jj0 * 32 + tt] = pack2(softplus_f(f0.x), softplus_f(f0.y));
            ((u64*)V2s)[jj1 * 32 + tt] = pack2(softplus_f(f1.x), softplus_f(f1.y));
        }
        __syncwarp();

        {
            u64 bp = ((const u64*)B3s)[tt];
            a0 = bp; a1 = bp;
            const float4* pr0 = (const float4*)(V2s + jj0 * 64);
            const float4* pr1 = (const float4*)(V2s + jj1 * 64);
            const u64* wv = (const u64*)W3Ts;
            #pragma unroll 4
            for (int c4 = 0; c4 < 16; c4++) {
                float4 p0 = pr0[c4];
                float4 p1 = pr1[c4];
                u64 w0 = wv[(c4 * 4 + 0) * 32 + tt];
                u64 w1 = wv[(c4 * 4 + 1) * 32 + tt];
                u64 w2 = wv[(c4 * 4 + 2) * 32 + tt];
                u64 w3 = wv[(c4 * 4 + 3) * 32 + tt];
                a0 = fma2(dup2(p0.x), w0, a0); a1 = fma2(dup2(p1.x), w0, a1);
                a0 = fma2(dup2(p0.y), w1, a0); a1 = fma2(dup2(p1.y), w1, a1);
                a0 = fma2(dup2(p0.z), w2, a0); a1 = fma2(dup2(p1.z), w2, a1);
                a0 = fma2(dup2(p0.w), w3, a0); a1 = fma2(dup2(p1.w), w3, a1);
            }
            const u64* xv = (const u64*)x;
            u64* ov = (u64*)out;
            int g0 = (m * 64 + j0 + jj0) * 32 + tt;
            int g1 = (m * 64 + j0 + jj1) * 32 + tt;
            float2 f0 = unpk2(a0), x0 = unpk2(xv[g0]);
            float2 f1 = unpk2(a1), x1 = unpk2(xv[g1]);
            ov[g0] = pack2(f0.x + x0.x, f0.y + x0.y);
            ov[g1] = pack2(f1.x + x1.x, f1.y + x1.y);
        }
    }
}

extern "C" void kernel_launch(void* const* d_in, const int* in_sizes, int n_in,
                              void* d_out, int out_size) {
    const float* x   = (const float*)d_in[0];
    const float* dist= (const float*)d_in[1];
    const float* W1  = (const float*)d_in[2];
    const float* b1  = (const float*)d_in[3];
    const float* W2  = (const float*)d_in[4];
    const float* b2  = (const float*)d_in[5];
    const float* W3  = (const float*)d_in[6];
    const float* b3  = (const float*)d_in[7];
    const float* Wd1 = (const float*)d_in[8];
    const float* bd1 = (const float*)d_in[9];
    const float* Wd2 = (const float*)d_in[10];
    const float* bd2 = (const float*)d_in[11];
    float* out = (float*)d_out;
    (void)in_sizes; (void)n_in; (void)out_size;

    cudaFuncSetAttribute(fused_kernel, cudaFuncAttributeMaxDynamicSharedMemorySize, MAIN_SMEM);
    fused_kernel<<<128, 1024, MAIN_SMEM>>>(x, dist, W1, b1, W2, b2, W3, b3,
                                           Wd1, bd1, Wd2, bd2, out);
}